// round 15
// baseline (speedup 1.0000x reference)
#include <cuda_runtime.h>
#include <math.h>

#define NB   32
#define NP   8732
#define NC   21
#define TOPK 200
#define NT   512
#define NP4  (NP / 4)      // 2183
#define FULLM 0xFFFFFFFFu

// Transposed, thresholded, order-mapped confidences: key32[b][c][p]
__device__ unsigned g_confT[(size_t)NB * NC * NP];

__device__ __forceinline__ unsigned mapkey(float f) {
    float sv = (f > 0.01f) ? f : -1.0f;
    unsigned u = __float_as_uint(sv);
    return (u & 0x80000000u) ? ~u : (u | 0x80000000u);
}

// ---------------------------------------------------------------------------
// Kernel 1: transpose + threshold + monotonic map; also zeroes class-0 output
// TP=256 tiles, 256 threads -> 8 CTAs/SM (smem 21.8 KB), latency-hiding occupancy
// ---------------------------------------------------------------------------
#define TP  256
#define S2S 260
__global__ __launch_bounds__(256)
void transpose_kernel(const float* __restrict__ conf, float* __restrict__ out) {
    __shared__ float s2[NC * S2S];          // 21840 B
    const int nt  = (NP + TP - 1) / TP;     // 35
    const int b   = blockIdx.x / nt;
    const int t   = blockIdx.x % nt;
    const int p0  = t * TP;
    const int np  = min(TP, NP - p0);       // 256 or 28 (both mult of 4)

    // block t==0 of each batch zeroes the class-0 output slab (1000 floats)
    if (t == 0 && threadIdx.x < 250) {
        float4* ob4 = (float4*)(out + (size_t)b * NC * (TOPK * 5));
        ob4[threadIdx.x] = make_float4(0.f, 0.f, 0.f, 0.f);
    }

    const float* src = conf + ((size_t)b * NP + p0) * NC;
    const float4* src4 = (const float4*)src;

    if (np == TP) {
        // fast path: full tile, strengths compile-time (no runtime divide)
        const int NV = TP * NC / 4;          // 1344
        for (int i = threadIdx.x; i < NV; i += 256) {
            float4 v = src4[i];
            int li = i * 4;
            #pragma unroll
            for (int q = 0; q < 4; q++) {
                int e = li + q;
                int p = e / NC;
                int c = e - p * NC;
                float f = (q == 0) ? v.x : (q == 1) ? v.y : (q == 2) ? v.z : v.w;
                s2[c * S2S + p] = f;
            }
        }
        __syncthreads();
        const int NG = TP / 4;               // 64
        for (int idx = threadIdx.x; idx < NC * NG; idx += 256) {
            int c = idx >> 6;                // /64
            int g = idx & (NG - 1);
            int p = g * 4;
            float4 v = *(const float4*)&s2[c * S2S + p];
            uint4 o;
            o.x = mapkey(v.x); o.y = mapkey(v.y);
            o.z = mapkey(v.z); o.w = mapkey(v.w);
            *(uint4*)(g_confT + ((size_t)b * NC + c) * NP + p0 + p) = o;
        }
    } else {
        const int n  = np * NC;
        const int nv = n >> 2;
        for (int i = threadIdx.x; i < nv; i += 256) {
            float4 v = src4[i];
            int li = i * 4;
            #pragma unroll
            for (int q = 0; q < 4; q++) {
                int e = li + q;
                int p = e / NC;
                int c = e - p * NC;
                float f = (q == 0) ? v.x : (q == 1) ? v.y : (q == 2) ? v.z : v.w;
                s2[c * S2S + p] = f;
            }
        }
        __syncthreads();
        const int ng = np >> 2;
        for (int idx = threadIdx.x; idx < NC * ng; idx += 256) {
            int c = idx / ng;
            int g = idx - c * ng;
            int p = g * 4;
            float4 v = *(const float4*)&s2[c * S2S + p];
            uint4 o;
            o.x = mapkey(v.x); o.y = mapkey(v.y);
            o.z = mapkey(v.z); o.w = mapkey(v.w);
            *(uint4*)(g_confT + ((size_t)b * NC + c) * NP + p0 + p) = o;
        }
    }
}

// ---------------------------------------------------------------------------
__device__ __forceinline__ float unmapf(unsigned m) {
    unsigned u = (m & 0x80000000u) ? (m ^ 0x80000000u) : ~m;
    return __uint_as_float(u);
}

// warp-aggregated smem histogram add (all 32 lanes converged)
__device__ __forceinline__ void aggHist(unsigned* hist, int d) {
    unsigned mm = __match_any_sync(FULLM, d);
    int lane = threadIdx.x & 31;
    if (lane == (__ffs(mm) - 1))
        atomicAdd(&hist[d], (unsigned)__popc(mm));
}

// ---------------------------------------------------------------------------
// Kernel 2: sample-histogram threshold + collect, sort, decode, NMS, write
// grid = NB * (NC-1): class 0 skipped entirely
// ---------------------------------------------------------------------------
__global__ __launch_bounds__(NT, 4)
void select_kernel(const float* __restrict__ loc,
                   const float* __restrict__ prior,
                   float* __restrict__ out) {
    const int bc  = blockIdx.x;
    const int b   = bc / (NC - 1);
    const int c   = 1 + bc % (NC - 1);
    const int blk = b * NC + c;
    const int tid = threadIdx.x;
    const int lane = tid & 31;
    const int wid  = tid >> 5;
    float* outBase = out + (size_t)blk * (TOPK * 5);

    // 32 KB arena: phase A = hist[8192]; phase B = defs/boxs/areas/scores/rows
    __shared__ __align__(16) unsigned char arena[32768];
    __shared__ unsigned ctr[8];
    __shared__ unsigned warpSums[16];
    __shared__ unsigned keepw[8];
    __shared__ unsigned validw[8];
    __shared__ unsigned hasroww[8];

    unsigned* hist = (unsigned*)arena;
    unsigned long long* defs = (unsigned long long*)arena;           // 0..4095
    float4*   boxs   = (float4*)(arena + 4096);                      // 224 * 16
    float*    areas  = (float*)(arena + 7680);                       // 224 * 4
    float*    scores = (float*)(arena + 8576);                       // 224 * 4
    unsigned* rows   = (unsigned*)(arena + 9472);                    // 224*8*4

    const unsigned* col  = g_confT + (size_t)blk * NP;
    const uint4*    col4 = (const uint4*)col;
    const int FULL_IT = NP4 / NT;           // 4
    const int TAIL    = NP4 - FULL_IT * NT; // 135

    // 2 register-resident samples per thread (1024 total, strided)
    const unsigned s0 = col[tid * 8 + 4];
    const unsigned s1 = col[(tid + 512) * 8 + 4];

    // ---------------- phase A: 13-bit sample histogram + bin threshold -----
    int t0bin;
    {
        uint4* h4 = (uint4*)hist;
        #pragma unroll
        for (int i = 0; i < 4; i++)
            h4[i * NT + tid] = make_uint4(0, 0, 0, 0);
        __syncthreads();

        aggHist(hist, (int)(s0 >> 19));
        aggHist(hist, (int)(s1 >> 19));
        __syncthreads();

        // suffix scan over 8192 bins descending; find bin where cum > 34
        int hi = 8191 - (tid << 4);
        unsigned bins[16];
        {
            const uint4* b4 = (const uint4*)(hist + (hi - 15));
            #pragma unroll
            for (int q = 0; q < 4; q++) {
                uint4 v = b4[q];
                bins[q * 4 + 0] = v.x; bins[q * 4 + 1] = v.y;
                bins[q * 4 + 2] = v.z; bins[q * 4 + 3] = v.w;
            }
        }
        unsigned lsum = 0;
        #pragma unroll
        for (int q = 0; q < 16; q++) lsum += bins[q];

        unsigned inc = lsum;
        #pragma unroll
        for (int off = 1; off < 32; off <<= 1) {
            unsigned nn = __shfl_up_sync(FULLM, inc, off);
            if (lane >= off) inc += nn;
        }
        if (lane == 31) warpSums[wid] = inc;
        __syncthreads();
        if (wid == 0) {
            unsigned v = (lane < 16) ? warpSums[lane] : 0;
            #pragma unroll
            for (int off = 1; off < 16; off <<= 1) {
                unsigned nn = __shfl_up_sync(FULLM, v, off);
                if (lane >= off) v += nn;
            }
            if (lane < 16) warpSums[lane] = v;
        }
        __syncthreads();
        unsigned ex = (wid ? warpSums[wid - 1] : 0) + inc - lsum;
        if (ex <= 34u && ex + lsum > 34u) {       // unique crossing thread
            unsigned acc = ex;
            #pragma unroll
            for (int q = 0; q < 16; q++) {
                unsigned hv = bins[15 - q];        // bin (hi - q)
                if (acc + hv > 34u) { ctr[1] = (unsigned)(hi - q); break; }
                acc += hv;
            }
        }
        __syncthreads();
        t0bin = (int)ctr[1];
    }

    // ---------------- collect keys >= (t<<19) with bin-step retry ----------
    unsigned Cm = 0, Cl = 0;
    int cnt = 0;
    {
        int t = t0bin;
        int wentUp = 0, wentDown = 0, attempt = 0;
        bool exact = false;
        while (true) {
            Cm = (t <= 0) ? 0u : ((unsigned)t << 19);
            Cl = 0;
            __syncthreads();
            if (tid == 0) ctr[0] = 0;
            __syncthreads();
            for (int it = 0; it <= FULL_IT; it++) {
                int i = it * NT + tid;
                bool valid = (it < FULL_IT) || (tid < TAIL);
                uint4 m4 = valid ? col4[i] : make_uint4(0, 0, 0, 0);
                bool p0v = valid && (m4.x >= Cm);
                bool p1v = valid && (m4.y >= Cm);
                bool p2v = valid && (m4.z >= Cm);
                bool p3v = valid && (m4.w >= Cm);
                unsigned b0 = __ballot_sync(FULLM, p0v);
                unsigned b1 = __ballot_sync(FULLM, p1v);
                unsigned b2 = __ballot_sync(FULLM, p2v);
                unsigned b3 = __ballot_sync(FULLM, p3v);
                unsigned c0 = (unsigned)__popc(b0);
                unsigned c1 = (unsigned)__popc(b1);
                unsigned c2 = (unsigned)__popc(b2);
                unsigned tot = c0 + c1 + c2 + (unsigned)__popc(b3);
                int base = 0;
                if (lane == 0 && tot) base = (int)atomicAdd(&ctr[0], tot);
                base = __shfl_sync(FULLM, base, 0);
                unsigned lt = (1u << lane) - 1u;
                unsigned idx0 = (unsigned)(i * 4);
                if (p0v) {
                    int pos = base + __popc(b0 & lt);
                    if (pos < 512)
                        defs[pos] = ((unsigned long long)m4.x << 32) | (unsigned)(~idx0);
                }
                if (p1v) {
                    int pos = base + (int)c0 + __popc(b1 & lt);
                    if (pos < 512)
                        defs[pos] = ((unsigned long long)m4.y << 32) | (unsigned)(~(idx0 + 1));
                }
                if (p2v) {
                    int pos = base + (int)(c0 + c1) + __popc(b2 & lt);
                    if (pos < 512)
                        defs[pos] = ((unsigned long long)m4.z << 32) | (unsigned)(~(idx0 + 2));
                }
                if (p3v) {
                    int pos = base + (int)(c0 + c1 + c2) + __popc(b3 & lt);
                    if (pos < 512)
                        defs[pos] = ((unsigned long long)m4.w << 32) | (unsigned)(~(idx0 + 3));
                }
            }
            __syncthreads();
            cnt = (int)ctr[0];
            if (cnt >= TOPK && cnt <= 512) break;
            attempt++;
            if (cnt > 512) { t++; wentUp = 1; } else { t--; wentDown = 1; }
            if (attempt >= 5 || (wentUp && wentDown) || t < 0 || t > 8191) {
                exact = true;
                break;
            }
        }

        if (exact) {
            // adversarial-input fallback: exact bitwise search on 64-bit keys
            unsigned long long Cp = 0;
            for (int bit = 63; bit >= 0; bit--) {
                unsigned long long trial = Cp | (1ull << bit);
                __syncthreads();
                if (tid == 0) ctr[7] = 0;
                __syncthreads();
                unsigned wcnt = 0;
                for (int it = 0; it <= FULL_IT; it++) {
                    int i = it * NT + tid;
                    bool valid = (it < FULL_IT) || (tid < TAIL);
                    uint4 m4 = valid ? col4[i] : make_uint4(0, 0, 0, 0);
                    #pragma unroll
                    for (int q = 0; q < 4; q++) {
                        unsigned m = (q == 0) ? m4.x : (q == 1) ? m4.y : (q == 2) ? m4.z : m4.w;
                        unsigned idx = (unsigned)(i * 4 + q);
                        unsigned long long key =
                            ((unsigned long long)m << 32) | (unsigned)(~idx);
                        wcnt += __popc(__ballot_sync(FULLM, valid && key >= trial));
                    }
                }
                if (lane == 0) atomicAdd(&ctr[7], wcnt);
                __syncthreads();
                if (ctr[7] >= TOPK) Cp = trial;
            }
            Cm = (unsigned)(Cp >> 32);
            Cl = (unsigned)Cp;
            __syncthreads();
            if (tid == 0) ctr[0] = 0;
            __syncthreads();
            for (int it = 0; it <= FULL_IT; it++) {
                int i = it * NT + tid;
                bool valid = (it < FULL_IT) || (tid < TAIL);
                uint4 m4 = valid ? col4[i] : make_uint4(0, 0, 0, 0);
                #pragma unroll
                for (int q = 0; q < 4; q++) {
                    unsigned m = (q == 0) ? m4.x : (q == 1) ? m4.y : (q == 2) ? m4.z : m4.w;
                    unsigned idx = (unsigned)(i * 4 + q);
                    bool p = valid && (m > Cm || (m == Cm && (~idx) >= Cl));
                    unsigned bal = __ballot_sync(FULLM, p);
                    int base = 0;
                    if (lane == 0 && bal) base = (int)atomicAdd(&ctr[0], (unsigned)__popc(bal));
                    base = __shfl_sync(FULLM, base, 0);
                    if (p) {
                        int pos = base + __popc(bal & ((1u << lane) - 1u));
                        if (pos < 512)
                            defs[pos] = ((unsigned long long)m << 32) | (unsigned)(~idx);
                    }
                }
            }
            __syncthreads();
            cnt = min((int)ctr[0], 512);
        }
    }

    for (int i = cnt + tid; i < 512; i += NT) defs[i] = 0ull;
    __syncthreads();

    // ---------------- hybrid bitonic sort of 512 u64 (ascending) -----------
    {
        unsigned long long a = defs[tid];
        for (int k = 2; k <= 512; k <<= 1) {
            for (int j = k >> 1; j > 0; j >>= 1) {
                if (j >= 32) {
                    defs[tid] = a;
                    __syncthreads();
                    unsigned long long bb = defs[tid ^ j];
                    bool ks = (((tid & j) == 0) == ((tid & k) == 0));
                    a = ((a < bb) == ks) ? a : bb;
                    __syncthreads();
                } else {
                    unsigned lo = (unsigned)a, hi2 = (unsigned)(a >> 32);
                    unsigned plo = __shfl_xor_sync(FULLM, lo, j);
                    unsigned phi = __shfl_xor_sync(FULLM, hi2, j);
                    unsigned long long bb = ((unsigned long long)phi << 32) | plo;
                    bool ks = (((tid & j) == 0) == ((tid & k) == 0));
                    a = ((a < bb) == ks) ? a : bb;
                }
            }
        }
        defs[tid] = a;
        __syncthreads();
    }

    // ---------------- decode top-200 + sentinel pad to 224 -----------------
    if (tid < TOPK) {
        unsigned long long key = defs[511 - tid];
        if (key) {
            unsigned m   = (unsigned)(key >> 32);
            unsigned idx = ~((unsigned)key);
            float sv = unmapf(m);
            float4 l  = __ldg((const float4*)loc + ((size_t)b * NP + idx));
            float4 pr = __ldg((const float4*)prior + idx);
            float cx = pr.x + l.x * 0.1f * pr.z;
            float cy = pr.y + l.y * 0.1f * pr.w;
            float w  = pr.z * expf(l.z * 0.2f);
            float h  = pr.w * expf(l.w * 0.2f);
            float x1 = cx - w * 0.5f;
            float y1 = cy - h * 0.5f;
            float x2 = x1 + w;
            float y2 = y1 + h;
            boxs[tid]  = make_float4(x1, y1, x2, y2);
            areas[tid] = (x2 - x1) * (y2 - y1);
            scores[tid] = sv;
        } else {
            boxs[tid]  = make_float4(1e30f, 1e30f, 1e30f, 1e30f);
            areas[tid] = 0.f;
            scores[tid] = -1.0f;
        }
    } else if (tid < 224) {
        boxs[tid]  = make_float4(1e30f, 1e30f, 1e30f, 1e30f);
        areas[tid] = 0.f;
        scores[tid] = -1.0f;
    }
    for (int i = tid; i < 224 * 8; i += NT) rows[i] = 0;
    __syncthreads();

    // -------- IoU bit-matrix: warp per (k-word, j-chunk), no bounds --------
    {
        for (int tt = wid; tt < 28; tt += 16) {
            int w = 0;
            while ((w + 1) * (w + 2) / 2 <= tt) w++;
            int jc = tt - w * (w + 1) / 2;
            int k = w * 32 + lane;
            float4 bk = boxs[k];
            float  ak = areas[k];
            int j0 = jc * 32;
            if (w == jc) {
                #pragma unroll 4
                for (int jj = 0; jj < 32; jj++) {
                    int j = j0 + jj;
                    float4 bj = boxs[j];
                    float  aj = areas[j];
                    float xx1 = fmaxf(bj.x, bk.x);
                    float yy1 = fmaxf(bj.y, bk.y);
                    float xx2 = fminf(bj.z, bk.z);
                    float yy2 = fminf(bj.w, bk.w);
                    float iw = fmaxf(xx2 - xx1, 0.0f);
                    float ih = fmaxf(yy2 - yy1, 0.0f);
                    float inter = iw * ih;
                    float uni = aj + ak - inter;
                    float iou = inter / uni;
                    bool hit = (lane > jj) && (iou > 0.45f);
                    unsigned bal = __ballot_sync(FULLM, hit);
                    if (lane == 0) rows[j * 8 + w] = bal;
                }
            } else {
                #pragma unroll 4
                for (int jj = 0; jj < 32; jj++) {
                    int j = j0 + jj;
                    float4 bj = boxs[j];
                    float  aj = areas[j];
                    float xx1 = fmaxf(bj.x, bk.x);
                    float yy1 = fmaxf(bj.y, bk.y);
                    float xx2 = fminf(bj.z, bk.z);
                    float yy2 = fminf(bj.w, bk.w);
                    float iw = fmaxf(xx2 - xx1, 0.0f);
                    float ih = fmaxf(yy2 - yy1, 0.0f);
                    float inter = iw * ih;
                    float uni = aj + ak - inter;
                    float iou = inter / uni;
                    bool hit = iou > 0.45f;
                    unsigned bal = __ballot_sync(FULLM, hit);
                    if (lane == 0) rows[j * 8 + w] = bal;
                }
            }
        }
    }
    __syncthreads();

    if (tid < 224) {
        int j = tid;
        bool val = scores[j] > 0.01f;
        uint4 r1 = *(const uint4*)&rows[j * 8];
        uint4 r2 = *(const uint4*)&rows[j * 8 + 4];
        unsigned r = r1.x | r1.y | r1.z | r1.w | r2.x | r2.y | r2.z;
        unsigned vb = __ballot_sync(FULLM, val);
        unsigned hb = __ballot_sync(FULLM, r != 0);
        if (lane == 0) { validw[wid] = vb; hasroww[wid] = hb; }
    }
    __syncthreads();

    // ---------------- serial greedy (bit ops) -------------------------------
    if (tid == 0) {
        unsigned sup[7] = {0, 0, 0, 0, 0, 0, 0};
        #pragma unroll
        for (int w = 0; w < 7; w++) {
            unsigned kwv = 0;
            unsigned rowm = hasroww[w];
            unsigned pend = validw[w] & ~sup[w];
            while (pend) {
                unsigned r = pend & rowm;
                if (!r) { kwv |= pend; break; }
                int bsh = __ffs(r) - 1;
                unsigned below = (1u << bsh) - 1u;
                kwv |= pend & below;
                kwv |= 1u << bsh;
                int j = w * 32 + bsh;
                uint4 r1 = *(const uint4*)&rows[j * 8];
                uint4 r2 = *(const uint4*)&rows[j * 8 + 4];
                sup[0] |= r1.x; sup[1] |= r1.y; sup[2] |= r1.z; sup[3] |= r1.w;
                sup[4] |= r2.x; sup[5] |= r2.y; sup[6] |= r2.z;
                unsigned above = ~((below << 1) | 1u);
                pend = validw[w] & ~sup[w] & above;
            }
            keepw[w] = kwv;
        }
    }
    __syncthreads();

    // -------- compact & write kept rows; zero only the tail ----------------
    int K = 0;
    #pragma unroll
    for (int ww = 0; ww < 7; ww++) K += __popc(keepw[ww]);

    if (tid < TOPK) {
        int w = tid >> 5, bs = tid & 31;
        unsigned kwv = keepw[w];
        if ((kwv >> bs) & 1u) {
            int pos = 0;
            #pragma unroll
            for (int ww = 0; ww < 7; ww++) if (ww < w) pos += __popc(keepw[ww]);
            pos += __popc(kwv & ((1u << bs) - 1u));
            float4 bx = boxs[tid];
            float* row = outBase + pos * 5;
            row[0] = scores[tid];
            row[1] = bx.x;
            row[2] = bx.y;
            row[3] = bx.z;
            row[4] = bx.w;
        }
    }
    for (int i = K * 5 + tid; i < TOPK * 5; i += NT) outBase[i] = 0.0f;
}

// ---------------------------------------------------------------------------
extern "C" void kernel_launch(void* const* d_in, const int* in_sizes, int n_in,
                              void* d_out, int out_size) {
    const float* loc   = (const float*)d_in[0];
    const float* conf  = (const float*)d_in[1];
    const float* prior = (const float*)d_in[2];
    float* out = (float*)d_out;

    const int nt = (NP + TP - 1) / TP;          // 35
    transpose_kernel<<<NB * nt, 256>>>(conf, out);
    select_kernel<<<NB * (NC - 1), NT>>>(loc, prior, out);
}

// round 16
// speedup vs baseline: 1.0714x; 1.0714x over previous
#include <cuda_runtime.h>
#include <math.h>

#define NB   32
#define NP   8732
#define NC   21
#define TOPK 200
#define NT   512
#define NP4  (NP / 4)      // 2183
#define FULLM 0xFFFFFFFFu

// Transposed, thresholded, order-mapped confidences: key32[b][c][p]
__device__ unsigned g_confT[(size_t)NB * NC * NP];

__device__ __forceinline__ unsigned mapkey(float f) {
    float sv = (f > 0.01f) ? f : -1.0f;
    unsigned u = __float_as_uint(sv);
    return (u & 0x80000000u) ? ~u : (u | 0x80000000u);
}

// ---------------------------------------------------------------------------
// Kernel 1: transpose + threshold + monotonic map; also zeroes class-0 output
// ---------------------------------------------------------------------------
#define TP  512
#define S2S 516
__global__ __launch_bounds__(512)
void transpose_kernel(const float* __restrict__ conf, float* __restrict__ out) {
    __shared__ float s2[NC * S2S];
    const int nt  = (NP + TP - 1) / TP;     // 18
    const int b   = blockIdx.x / nt;
    const int t   = blockIdx.x % nt;
    const int p0  = t * TP;
    const int np  = min(TP, NP - p0);

    if (t == 0 && threadIdx.x < 250) {
        float4* ob4 = (float4*)(out + (size_t)b * NC * (TOPK * 5));
        ob4[threadIdx.x] = make_float4(0.f, 0.f, 0.f, 0.f);
    }

    const float* src = conf + ((size_t)b * NP + p0) * NC;
    const float4* src4 = (const float4*)src;

    if (np == TP) {
        // fast path: full tile, strengths compile-time (no runtime divide)
        const int NV = TP * NC / 4;          // 2688
        for (int i = threadIdx.x; i < NV; i += 512) {
            float4 v = src4[i];
            int li = i * 4;
            #pragma unroll
            for (int q = 0; q < 4; q++) {
                int e = li + q;
                int p = e / NC;
                int c = e - p * NC;
                float f = (q == 0) ? v.x : (q == 1) ? v.y : (q == 2) ? v.z : v.w;
                s2[c * S2S + p] = f;
            }
        }
        __syncthreads();
        const int NG = TP / 4;               // 128
        for (int idx = threadIdx.x; idx < NC * NG; idx += 512) {
            int c = idx >> 7;                // /128
            int g = idx & (NG - 1);
            int p = g * 4;
            float4 v = *(const float4*)&s2[c * S2S + p];
            uint4 o;
            o.x = mapkey(v.x); o.y = mapkey(v.y);
            o.z = mapkey(v.z); o.w = mapkey(v.w);
            *(uint4*)(g_confT + ((size_t)b * NC + c) * NP + p0 + p) = o;
        }
    } else {
        const int n  = np * NC;
        const int nv = n >> 2;
        for (int i = threadIdx.x; i < nv; i += 512) {
            float4 v = src4[i];
            int li = i * 4;
            #pragma unroll
            for (int q = 0; q < 4; q++) {
                int e = li + q;
                int p = e / NC;
                int c = e - p * NC;
                float f = (q == 0) ? v.x : (q == 1) ? v.y : (q == 2) ? v.z : v.w;
                s2[c * S2S + p] = f;
            }
        }
        __syncthreads();
        const int ng = np >> 2;
        for (int idx = threadIdx.x; idx < NC * ng; idx += 512) {
            int c = idx / ng;
            int g = idx - c * ng;
            int p = g * 4;
            float4 v = *(const float4*)&s2[c * S2S + p];
            uint4 o;
            o.x = mapkey(v.x); o.y = mapkey(v.y);
            o.z = mapkey(v.z); o.w = mapkey(v.w);
            *(uint4*)(g_confT + ((size_t)b * NC + c) * NP + p0 + p) = o;
        }
    }
}

// ---------------------------------------------------------------------------
__device__ __forceinline__ float unmapf(unsigned m) {
    unsigned u = (m & 0x80000000u) ? (m ^ 0x80000000u) : ~m;
    return __uint_as_float(u);
}

// warp-aggregated smem histogram add (all 32 lanes converged)
__device__ __forceinline__ void aggHist(unsigned* hist, int d) {
    unsigned mm = __match_any_sync(FULLM, d);
    int lane = threadIdx.x & 31;
    if (lane == (__ffs(mm) - 1))
        atomicAdd(&hist[d], (unsigned)__popc(mm));
}

// ---------------------------------------------------------------------------
// Kernel 2: sample-histogram threshold + collect, sort, decode, NMS, write
// grid = NB * (NC-1): class 0 skipped entirely
// ---------------------------------------------------------------------------
__global__ __launch_bounds__(NT, 4)
void select_kernel(const float* __restrict__ loc,
                   const float* __restrict__ prior,
                   float* __restrict__ out) {
    const int bc  = blockIdx.x;
    const int b   = bc / (NC - 1);
    const int c   = 1 + bc % (NC - 1);
    const int blk = b * NC + c;
    const int tid = threadIdx.x;
    const int lane = tid & 31;
    const int wid  = tid >> 5;
    float* outBase = out + (size_t)blk * (TOPK * 5);

    {
        float4* ob4 = (float4*)outBase;
        for (int i = tid; i < (TOPK * 5) / 4; i += NT)
            ob4[i] = make_float4(0.f, 0.f, 0.f, 0.f);
    }

    // 32 KB arena: phase A = hist[8192]; phase B = defs/boxs/areas/scores/rows
    __shared__ __align__(16) unsigned char arena[32768];
    __shared__ unsigned ctr[8];
    __shared__ unsigned warpSums[16];
    __shared__ unsigned keepw[8];
    __shared__ unsigned validw[8];
    __shared__ unsigned hasroww[8];

    unsigned* hist = (unsigned*)arena;
    unsigned long long* defs = (unsigned long long*)arena;           // 0..4095
    float4*   boxs   = (float4*)(arena + 4096);                      // 224 * 16
    float*    areas  = (float*)(arena + 7680);                       // 224 * 4
    float*    scores = (float*)(arena + 8576);                       // 224 * 4
    unsigned* rows   = (unsigned*)(arena + 9472);                    // 224*8*4

    const unsigned* col  = g_confT + (size_t)blk * NP;
    const uint4*    col4 = (const uint4*)col;
    const int FULL_IT = NP4 / NT;           // 4
    const int TAIL    = NP4 - FULL_IT * NT; // 135

    // 2 register-resident samples per thread (1024 total, strided)
    const unsigned s0 = col[tid * 8 + 4];
    const unsigned s1 = col[(tid + 512) * 8 + 4];

    // ---------------- phase A: 13-bit sample histogram + bin threshold -----
    int t0bin;
    {
        uint4* h4 = (uint4*)hist;
        #pragma unroll
        for (int i = 0; i < 4; i++)
            h4[i * NT + tid] = make_uint4(0, 0, 0, 0);
        __syncthreads();

        aggHist(hist, (int)(s0 >> 19));
        aggHist(hist, (int)(s1 >> 19));
        __syncthreads();

        // suffix scan over 8192 bins descending; find bin where cum > 34
        int hi = 8191 - (tid << 4);
        unsigned bins[16];
        {
            const uint4* b4 = (const uint4*)(hist + (hi - 15));
            #pragma unroll
            for (int q = 0; q < 4; q++) {
                uint4 v = b4[q];
                bins[q * 4 + 0] = v.x; bins[q * 4 + 1] = v.y;
                bins[q * 4 + 2] = v.z; bins[q * 4 + 3] = v.w;
            }
        }
        unsigned lsum = 0;
        #pragma unroll
        for (int q = 0; q < 16; q++) lsum += bins[q];

        unsigned inc = lsum;
        #pragma unroll
        for (int off = 1; off < 32; off <<= 1) {
            unsigned nn = __shfl_up_sync(FULLM, inc, off);
            if (lane >= off) inc += nn;
        }
        if (lane == 31) warpSums[wid] = inc;
        __syncthreads();
        if (wid == 0) {
            unsigned v = (lane < 16) ? warpSums[lane] : 0;
            #pragma unroll
            for (int off = 1; off < 16; off <<= 1) {
                unsigned nn = __shfl_up_sync(FULLM, v, off);
                if (lane >= off) v += nn;
            }
            if (lane < 16) warpSums[lane] = v;
        }
        __syncthreads();
        unsigned ex = (wid ? warpSums[wid - 1] : 0) + inc - lsum;
        if (ex <= 34u && ex + lsum > 34u) {       // unique crossing thread
            unsigned acc = ex;
            #pragma unroll
            for (int q = 0; q < 16; q++) {
                unsigned hv = bins[15 - q];        // bin (hi - q)
                if (acc + hv > 34u) { ctr[1] = (unsigned)(hi - q); break; }
                acc += hv;
            }
        }
        __syncthreads();
        t0bin = (int)ctr[1];
    }

    // ---------------- collect keys >= (t<<19) with bin-step retry ----------
    unsigned Cm = 0, Cl = 0;
    int cnt = 0;
    {
        int t = t0bin;
        int wentUp = 0, wentDown = 0, attempt = 0;
        bool exact = false;
        while (true) {
            Cm = (t <= 0) ? 0u : ((unsigned)t << 19);
            Cl = 0;
            __syncthreads();
            if (tid == 0) ctr[0] = 0;
            __syncthreads();
            for (int it = 0; it <= FULL_IT; it++) {
                int i = it * NT + tid;
                bool valid = (it < FULL_IT) || (tid < TAIL);
                uint4 m4 = valid ? col4[i] : make_uint4(0, 0, 0, 0);
                bool p0v = valid && (m4.x >= Cm);
                bool p1v = valid && (m4.y >= Cm);
                bool p2v = valid && (m4.z >= Cm);
                bool p3v = valid && (m4.w >= Cm);
                unsigned b0 = __ballot_sync(FULLM, p0v);
                unsigned b1 = __ballot_sync(FULLM, p1v);
                unsigned b2 = __ballot_sync(FULLM, p2v);
                unsigned b3 = __ballot_sync(FULLM, p3v);
                unsigned c0 = (unsigned)__popc(b0);
                unsigned c1 = (unsigned)__popc(b1);
                unsigned c2 = (unsigned)__popc(b2);
                unsigned tot = c0 + c1 + c2 + (unsigned)__popc(b3);
                int base = 0;
                if (lane == 0 && tot) base = (int)atomicAdd(&ctr[0], tot);
                base = __shfl_sync(FULLM, base, 0);
                unsigned lt = (1u << lane) - 1u;
                unsigned idx0 = (unsigned)(i * 4);
                if (p0v) {
                    int pos = base + __popc(b0 & lt);
                    if (pos < 512)
                        defs[pos] = ((unsigned long long)m4.x << 32) | (unsigned)(~idx0);
                }
                if (p1v) {
                    int pos = base + (int)c0 + __popc(b1 & lt);
                    if (pos < 512)
                        defs[pos] = ((unsigned long long)m4.y << 32) | (unsigned)(~(idx0 + 1));
                }
                if (p2v) {
                    int pos = base + (int)(c0 + c1) + __popc(b2 & lt);
                    if (pos < 512)
                        defs[pos] = ((unsigned long long)m4.z << 32) | (unsigned)(~(idx0 + 2));
                }
                if (p3v) {
                    int pos = base + (int)(c0 + c1 + c2) + __popc(b3 & lt);
                    if (pos < 512)
                        defs[pos] = ((unsigned long long)m4.w << 32) | (unsigned)(~(idx0 + 3));
                }
            }
            __syncthreads();
            cnt = (int)ctr[0];
            if (cnt >= TOPK && cnt <= 512) break;
            attempt++;
            if (cnt > 512) { t++; wentUp = 1; } else { t--; wentDown = 1; }
            if (attempt >= 5 || (wentUp && wentDown) || t < 0 || t > 8191) {
                exact = true;
                break;
            }
        }

        if (exact) {
            // adversarial-input fallback: exact bitwise search on 64-bit keys
            unsigned long long Cp = 0;
            for (int bit = 63; bit >= 0; bit--) {
                unsigned long long trial = Cp | (1ull << bit);
                __syncthreads();
                if (tid == 0) ctr[7] = 0;
                __syncthreads();
                unsigned wcnt = 0;
                for (int it = 0; it <= FULL_IT; it++) {
                    int i = it * NT + tid;
                    bool valid = (it < FULL_IT) || (tid < TAIL);
                    uint4 m4 = valid ? col4[i] : make_uint4(0, 0, 0, 0);
                    #pragma unroll
                    for (int q = 0; q < 4; q++) {
                        unsigned m = (q == 0) ? m4.x : (q == 1) ? m4.y : (q == 2) ? m4.z : m4.w;
                        unsigned idx = (unsigned)(i * 4 + q);
                        unsigned long long key =
                            ((unsigned long long)m << 32) | (unsigned)(~idx);
                        wcnt += __popc(__ballot_sync(FULLM, valid && key >= trial));
                    }
                }
                if (lane == 0) atomicAdd(&ctr[7], wcnt);
                __syncthreads();
                if (ctr[7] >= TOPK) Cp = trial;
            }
            Cm = (unsigned)(Cp >> 32);
            Cl = (unsigned)Cp;
            __syncthreads();
            if (tid == 0) ctr[0] = 0;
            __syncthreads();
            for (int it = 0; it <= FULL_IT; it++) {
                int i = it * NT + tid;
                bool valid = (it < FULL_IT) || (tid < TAIL);
                uint4 m4 = valid ? col4[i] : make_uint4(0, 0, 0, 0);
                #pragma unroll
                for (int q = 0; q < 4; q++) {
                    unsigned m = (q == 0) ? m4.x : (q == 1) ? m4.y : (q == 2) ? m4.z : m4.w;
                    unsigned idx = (unsigned)(i * 4 + q);
                    bool p = valid && (m > Cm || (m == Cm && (~idx) >= Cl));
                    unsigned bal = __ballot_sync(FULLM, p);
                    int base = 0;
                    if (lane == 0 && bal) base = (int)atomicAdd(&ctr[0], (unsigned)__popc(bal));
                    base = __shfl_sync(FULLM, base, 0);
                    if (p) {
                        int pos = base + __popc(bal & ((1u << lane) - 1u));
                        if (pos < 512)
                            defs[pos] = ((unsigned long long)m << 32) | (unsigned)(~idx);
                    }
                }
            }
            __syncthreads();
            cnt = min((int)ctr[0], 512);
        }
    }

    for (int i = cnt + tid; i < 512; i += NT) defs[i] = 0ull;
    __syncthreads();

    // ---------------- hybrid bitonic sort of 512 u64 (ascending) -----------
    {
        unsigned long long a = defs[tid];
        for (int k = 2; k <= 512; k <<= 1) {
            for (int j = k >> 1; j > 0; j >>= 1) {
                if (j >= 32) {
                    defs[tid] = a;
                    __syncthreads();
                    unsigned long long bb = defs[tid ^ j];
                    bool ks = (((tid & j) == 0) == ((tid & k) == 0));
                    a = ((a < bb) == ks) ? a : bb;
                    __syncthreads();
                } else {
                    unsigned lo = (unsigned)a, hi2 = (unsigned)(a >> 32);
                    unsigned plo = __shfl_xor_sync(FULLM, lo, j);
                    unsigned phi = __shfl_xor_sync(FULLM, hi2, j);
                    unsigned long long bb = ((unsigned long long)phi << 32) | plo;
                    bool ks = (((tid & j) == 0) == ((tid & k) == 0));
                    a = ((a < bb) == ks) ? a : bb;
                }
            }
        }
        defs[tid] = a;
        __syncthreads();
    }

    // ---------------- decode top-200 + sentinel pad to 224 -----------------
    if (tid < TOPK) {
        unsigned long long key = defs[511 - tid];
        if (key) {
            unsigned m   = (unsigned)(key >> 32);
            unsigned idx = ~((unsigned)key);
            float sv = unmapf(m);
            float4 l  = __ldg((const float4*)loc + ((size_t)b * NP + idx));
            float4 pr = __ldg((const float4*)prior + idx);
            float cx = pr.x + l.x * 0.1f * pr.z;
            float cy = pr.y + l.y * 0.1f * pr.w;
            float w  = pr.z * expf(l.z * 0.2f);
            float h  = pr.w * expf(l.w * 0.2f);
            float x1 = cx - w * 0.5f;
            float y1 = cy - h * 0.5f;
            float x2 = x1 + w;
            float y2 = y1 + h;
            boxs[tid]  = make_float4(x1, y1, x2, y2);
            areas[tid] = (x2 - x1) * (y2 - y1);
            scores[tid] = sv;
        } else {
            boxs[tid]  = make_float4(1e30f, 1e30f, 1e30f, 1e30f);
            areas[tid] = 0.f;
            scores[tid] = -1.0f;
        }
    } else if (tid < 224) {
        boxs[tid]  = make_float4(1e30f, 1e30f, 1e30f, 1e30f);
        areas[tid] = 0.f;
        scores[tid] = -1.0f;
    }
    for (int i = tid; i < 224 * 8; i += NT) rows[i] = 0;
    __syncthreads();

    // -------- IoU bit-matrix: warp per (k-word, j-chunk), no bounds --------
    {
        for (int tt = wid; tt < 28; tt += 16) {
            int w = 0;
            while ((w + 1) * (w + 2) / 2 <= tt) w++;
            int jc = tt - w * (w + 1) / 2;
            int k = w * 32 + lane;
            float4 bk = boxs[k];
            float  ak = areas[k];
            int j0 = jc * 32;
            if (w == jc) {
                #pragma unroll 4
                for (int jj = 0; jj < 32; jj++) {
                    int j = j0 + jj;
                    float4 bj = boxs[j];
                    float  aj = areas[j];
                    float xx1 = fmaxf(bj.x, bk.x);
                    float yy1 = fmaxf(bj.y, bk.y);
                    float xx2 = fminf(bj.z, bk.z);
                    float yy2 = fminf(bj.w, bk.w);
                    float iw = fmaxf(xx2 - xx1, 0.0f);
                    float ih = fmaxf(yy2 - yy1, 0.0f);
                    float inter = iw * ih;
                    float uni = aj + ak - inter;
                    float iou = inter / uni;
                    bool hit = (lane > jj) && (iou > 0.45f);
                    unsigned bal = __ballot_sync(FULLM, hit);
                    if (lane == 0) rows[j * 8 + w] = bal;
                }
            } else {
                #pragma unroll 4
                for (int jj = 0; jj < 32; jj++) {
                    int j = j0 + jj;
                    float4 bj = boxs[j];
                    float  aj = areas[j];
                    float xx1 = fmaxf(bj.x, bk.x);
                    float yy1 = fmaxf(bj.y, bk.y);
                    float xx2 = fminf(bj.z, bk.z);
                    float yy2 = fminf(bj.w, bk.w);
                    float iw = fmaxf(xx2 - xx1, 0.0f);
                    float ih = fmaxf(yy2 - yy1, 0.0f);
                    float inter = iw * ih;
                    float uni = aj + ak - inter;
                    float iou = inter / uni;
                    bool hit = iou > 0.45f;
                    unsigned bal = __ballot_sync(FULLM, hit);
                    if (lane == 0) rows[j * 8 + w] = bal;
                }
            }
        }
    }
    __syncthreads();

    if (tid < 224) {
        int j = tid;
        bool val = scores[j] > 0.01f;
        uint4 r1 = *(const uint4*)&rows[j * 8];
        uint4 r2 = *(const uint4*)&rows[j * 8 + 4];
        unsigned r = r1.x | r1.y | r1.z | r1.w | r2.x | r2.y | r2.z;
        unsigned vb = __ballot_sync(FULLM, val);
        unsigned hb = __ballot_sync(FULLM, r != 0);
        if (lane == 0) { validw[wid] = vb; hasroww[wid] = hb; }
    }
    __syncthreads();

    // ---------------- serial greedy (bit ops) -------------------------------
    if (tid == 0) {
        unsigned sup[7] = {0, 0, 0, 0, 0, 0, 0};
        #pragma unroll
        for (int w = 0; w < 7; w++) {
            unsigned kwv = 0;
            unsigned rowm = hasroww[w];
            unsigned pend = validw[w] & ~sup[w];
            while (pend) {
                unsigned r = pend & rowm;
                if (!r) { kwv |= pend; break; }
                int bsh = __ffs(r) - 1;
                unsigned below = (1u << bsh) - 1u;
                kwv |= pend & below;
                kwv |= 1u << bsh;
                int j = w * 32 + bsh;
                uint4 r1 = *(const uint4*)&rows[j * 8];
                uint4 r2 = *(const uint4*)&rows[j * 8 + 4];
                sup[0] |= r1.x; sup[1] |= r1.y; sup[2] |= r1.z; sup[3] |= r1.w;
                sup[4] |= r2.x; sup[5] |= r2.y; sup[6] |= r2.z;
                unsigned above = ~((below << 1) | 1u);
                pend = validw[w] & ~sup[w] & above;
            }
            keepw[w] = kwv;
        }
    }
    __syncthreads();

    // ---------------- compact & write ---------------------------------------
    if (tid < TOPK) {
        int w = tid >> 5, bs = tid & 31;
        unsigned kwv = keepw[w];
        if ((kwv >> bs) & 1u) {
            int pos = 0;
            #pragma unroll
            for (int ww = 0; ww < 7; ww++) if (ww < w) pos += __popc(keepw[ww]);
            pos += __popc(kwv & ((1u << bs) - 1u));
            float4 bx = boxs[tid];
            float* row = outBase + pos * 5;
            row[0] = scores[tid];
            row[1] = bx.x;
            row[2] = bx.y;
            row[3] = bx.z;
            row[4] = bx.w;
        }
    }
}

// ---------------------------------------------------------------------------
extern "C" void kernel_launch(void* const* d_in, const int* in_sizes, int n_in,
                              void* d_out, int out_size) {
    const float* loc   = (const float*)d_in[0];
    const float* conf  = (const float*)d_in[1];
    const float* prior = (const float*)d_in[2];
    float* out = (float*)d_out;

    const int nt = (NP + TP - 1) / TP;          // 18
    transpose_kernel<<<NB * nt, 512>>>(conf, out);
    select_kernel<<<NB * (NC - 1), NT>>>(loc, prior, out);
}